// round 12
// baseline (speedup 1.0000x reference)
#include <cuda_runtime.h>
#include <stdint.h>

#define NBATCH 8
#define NCLS   80
#define ROWS   17328                  // A*HW = 3*5776
#define PERB   (ROWS * NCLS)          // 1386240 elements per batch
#define PERB4  (PERB / 4)             // 346560 float4 per batch
#define SLICE4 (PERB4 / NCLS)         // 4332 float4 per CTA scatter slice
#define NTHR   320
#define TOPK   200
#define CAP    1024                   // staging / sort buffer capacity
#define CAP_G  768                    // global per-(b,c) candidate list capacity
#define KW     7                      // words actually used for bitmasks
#define KW8    8                      // padded stride (uint4 x2 per row)
#define NBC    (NBATCH * NCLS)
#define NFINE  9
#define NLAD   11
#define TH     0.98f

// Global scratch (static, zero-initialized at module load)
__device__ unsigned long long g_cand[NBC * CAP_G];   // ~3.9 MB
__device__ int g_ccnt[NBC];                          // reset by each CTA at end
__device__ int g_done[NBATCH];                       // monotonic barrier counters

__device__ __forceinline__ unsigned long long make_key(unsigned int scbits, int row) {
    return ((unsigned long long)scbits << 32) | (unsigned int)(~row);
}

// Cold path: staging overflow -> push straight to the per-(b,c) global list.
__device__ __noinline__ void direct_push(unsigned long long pk, int b) {
    unsigned int rem = (unsigned int)pk;
    int row = rem / NCLS;
    int cls = rem - row * NCLS;
    int dbc = b * NCLS + cls;
    int pos = atomicAdd(&g_ccnt[dbc], 1);
    if (pos < CAP_G)
        g_cand[dbc * CAP_G + pos] = make_key((unsigned int)(pk >> 32), row);
}

// Hot path: 4-bit hitmask + warp-uniform vote loop; one divergent block/round.
__device__ __forceinline__ void scan4(float4 v, int e0,
                                      unsigned long long* stage, int* scnt, int b) {
    unsigned int h = (v.x > TH ? 1u : 0u) | (v.y > TH ? 2u : 0u)
                   | (v.z > TH ? 4u : 0u) | (v.w > TH ? 8u : 0u);
    while (__any_sync(0xffffffffu, h)) {
        bool act = (h != 0u);
        int u = __ffs(h) - 1;
        h &= h - 1;
        if (act) {
            float val = (u == 0) ? v.x : (u == 1) ? v.y : (u == 2) ? v.z : v.w;
            unsigned long long pk =
                ((unsigned long long)__float_as_uint(val) << 32) | (unsigned int)(e0 + u);
            int pos = atomicAdd(scnt, 1);
            if (pos < CAP) stage[pos] = pk;
            else direct_push(pk, b);
        }
    }
}

// ---------------------------------------------------------------------------
// Fused kernel: one CTA per (batch, class).
// Phase 1: scan 1/80 of this batch's scores into SMEM staging, then distribute
//          staged candidates to per-(b,c) global lists.
// Phase 2: per-batch barrier, then pivot-refine + sort + greedy NMS.
// ---------------------------------------------------------------------------
__global__ void __launch_bounds__(NTHR, 5)
fused_kernel(const float4* __restrict__ s4,
             const float*  __restrict__ boxes,
             const float*  __restrict__ scores,
             float*        __restrict__ out) {
    const int tid  = threadIdx.x;
    const int lane = tid & 31;
    const int wid  = tid >> 5;
    const int bc   = blockIdx.x;
    const int b    = bc / NCLS;
    const int c    = bc % NCLS;

    __shared__ unsigned long long keys[CAP];         // staging, then sort buffer
    __shared__ float4 s_box4[TOPK];
    __shared__ float s_area[TOPK], s_sc[TOPK];
    __shared__ unsigned int sup[(TOPK + 1) * KW8];
    __shared__ unsigned int s_keepw[KW];
    __shared__ int s_num, s_fcnt[NFINE], s_pcnt[NLAD];

    // ================= Phase 1: scan slice into SMEM staging =================
    if (tid == 0) s_num = 0;
    __syncthreads();
    {
        const float4* p = s4 + (size_t)bc * SLICE4;  // b*PERB4 + c*SLICE4
        const int rbase = c * (SLICE4 * 4);          // batch-relative element base
        #pragma unroll
        for (int g = 0; g < 3; g++) {
            int i0 = tid + g * (4 * NTHR);
            float4 v0 = __ldcs(&p[i0]);
            float4 v1 = __ldcs(&p[i0 + NTHR]);
            float4 v2 = __ldcs(&p[i0 + 2 * NTHR]);
            float4 v3 = __ldcs(&p[i0 + 3 * NTHR]);
            scan4(v0, rbase + i0 * 4,              keys, &s_num, b);
            scan4(v1, rbase + (i0 + NTHR) * 4,     keys, &s_num, b);
            scan4(v2, rbase + (i0 + 2 * NTHR) * 4, keys, &s_num, b);
            scan4(v3, rbase + (i0 + 3 * NTHR) * 4, keys, &s_num, b);
        }
        {   // iterations 12 (full) and 13 (guarded): 14*320 = 4480 >= 4332
            int i0 = tid + 12 * NTHR;
            int i1 = tid + 13 * NTHR;
            float4 v0 = __ldcs(&p[i0]);
            float4 v1 = (i1 < SLICE4) ? __ldcs(&p[i1])
                                      : make_float4(0.f, 0.f, 0.f, 0.f);
            scan4(v0, rbase + i0 * 4, keys, &s_num, b);
            scan4(v1, rbase + i1 * 4, keys, &s_num, b);
        }
    }
    __syncthreads();
    // ---- Distribute staged candidates to per-(b,c) global lists.
    {
        int nstage = s_num; if (nstage > CAP) nstage = CAP;
        for (int k = tid; k < nstage; k += NTHR) {
            unsigned long long pk = keys[k];
            unsigned int rem = (unsigned int)pk;
            int row = rem / NCLS;
            int cls = rem - row * NCLS;
            int dbc = b * NCLS + cls;
            int pos = atomicAdd(&g_ccnt[dbc], 1);
            if (pos < CAP_G)
                g_cand[dbc * CAP_G + pos] = make_key((unsigned int)(pk >> 32), row);
        }
    }
    // ---- Per-batch barrier: 80 arrivals on a monotonic counter.
    __syncthreads();
    if (tid == 0) {
        __threadfence();
        int old = atomicAdd(&g_done[b], 1);
        int target = old - (old % NCLS) + NCLS;
        const volatile int* dp = (const volatile int*)&g_done[b];
        while (*dp < target) __nanosleep(64);
        __threadfence();
    }
    __syncthreads();

    // ================= Phase 2: NMS for (b, c) =================
    const int cnt098 = g_ccnt[bc];

    if (tid < NFINE) s_fcnt[tid] = 0;
    if (tid == 0) s_num = 0;
    __syncthreads();

    int cnt;
    if (cnt098 >= TOPK && cnt098 <= CAP_G) {
        // ---- Fast path: list is complete and holds >= 200 candidates.
        unsigned long long kreg[3];
        const unsigned long long* src = g_cand + (size_t)bc * CAP_G;
        #pragma unroll
        for (int r = 0; r < 3; r++) {
            int k = tid + r * NTHR;
            kreg[r] = (k < cnt098) ? src[k] : 0ull;
        }
        const float FL[NFINE] = {0.99500f, 0.99375f, 0.99250f, 0.99125f, 0.99000f,
                                 0.98875f, 0.98750f, 0.98625f, 0.98500f};
        int lc[NFINE];
        #pragma unroll
        for (int f = 0; f < NFINE; f++) lc[f] = 0;
        #pragma unroll
        for (int r = 0; r < 3; r++) {
            float sc = __uint_as_float((unsigned int)(kreg[r] >> 32));
            #pragma unroll
            for (int f = 0; f < NFINE; f++) lc[f] += (sc > FL[f]);
        }
        #pragma unroll
        for (int f = 0; f < NFINE; f++) {
            int ws = __reduce_add_sync(0xffffffffu, lc[f]);
            if (lane == 0 && ws) atomicAdd(&s_fcnt[f], ws);
        }
        __syncthreads();
        float pivot = TH;
        #pragma unroll
        for (int f = NFINE - 1; f >= 0; f--)
            if (s_fcnt[f] >= TOPK) pivot = FL[f];
        #pragma unroll
        for (int r = 0; r < 3; r++) {
            float sc = __uint_as_float((unsigned int)(kreg[r] >> 32));
            if (sc > pivot) {
                int pos = atomicAdd(&s_num, 1);
                keys[pos] = kreg[r];
            }
        }
        __syncthreads();
        cnt = s_num;
    } else {
        // ---- Fallback (statistically never): full strided rescan with ladder.
        if (tid < NLAD) s_pcnt[tid] = 0;
        __syncthreads();
        const float PL[NLAD] = {0.9950f, 0.9925f, 0.9900f, 0.9875f, 0.9850f,
                                0.98f, 0.96f, 0.92f, 0.84f, 0.68f, 0.50f};
        const float* col = scores + (size_t)b * PERB + c;
        int lc[NLAD];
        #pragma unroll
        for (int l = 0; l < NLAD; l++) lc[l] = 0;
        for (int i = tid; i < ROWS; i += NTHR) {
            float v = col[(size_t)i * NCLS];
            #pragma unroll
            for (int l = 0; l < NLAD; l++) lc[l] += (v > PL[l]);
        }
        #pragma unroll
        for (int l = 0; l < NLAD; l++) {
            int ws = __reduce_add_sync(0xffffffffu, lc[l]);
            if (lane == 0 && ws) atomicAdd(&s_pcnt[l], ws);
        }
        __syncthreads();
        const int n05 = s_pcnt[NLAD - 1];
        const int target = (n05 < TOPK) ? n05 : TOPK;
        float pivot = 0.50f;
        #pragma unroll
        for (int l = NLAD - 1; l >= 0; l--)
            if (s_pcnt[l] >= target) pivot = PL[l];
        for (int i = tid; i < ROWS; i += NTHR) {
            float v = col[(size_t)i * NCLS];
            if (v > pivot) {
                int pos = atomicAdd(&s_num, 1);
                if (pos < CAP) keys[pos] = make_key(__float_as_uint(v), i);
            }
        }
        __syncthreads();
        cnt = s_num; if (cnt > CAP) cnt = CAP;
    }

    // ---- Sort descending. Register/shuffle bitonic on threads 0..255.
    if (cnt <= 256) {
        for (int i = cnt + tid; i < 256; i += NTHR) keys[i] = 0ull;
        __syncthreads();
        unsigned long long key = (tid < 256) ? keys[tid] : 0ull;
        #pragma unroll
        for (int k = 2; k <= 256; k <<= 1) {
            #pragma unroll
            for (int j = k >> 1; j > 0; j >>= 1) {
                unsigned long long other;
                if (j >= 32) {
                    if (tid < 256) keys[tid] = key;
                    __syncthreads();
                    other = (tid < 256) ? keys[tid ^ j] : 0ull;
                    __syncthreads();
                } else {
                    other = __shfl_xor_sync(0xffffffffu, key, j);
                }
                bool keep_max = ((tid & k) == 0) == ((tid & j) == 0);
                key = ((key > other) == keep_max) ? key : other;
            }
        }
        if (tid < 256) keys[tid] = key;
        __syncthreads();
    } else {
        int P = 512; while (P < cnt) P <<= 1;
        for (int i = cnt + tid; i < P; i += NTHR) keys[i] = 0ull;
        __syncthreads();
        for (int k = 2; k <= P; k <<= 1) {
            for (int j = k >> 1; j > 0; j >>= 1) {
                for (int i = tid; i < P; i += NTHR) {
                    int l = i ^ j;
                    if (l > i) {
                        unsigned long long a = keys[i], d = keys[l];
                        bool sw = ((i & k) == 0) ? (a < d) : (a > d);
                        if (sw) { keys[i] = d; keys[l] = a; }
                    }
                }
                __syncthreads();
            }
        }
    }

    const int n_top = (cnt < TOPK) ? cnt : TOPK;

    // ---- Gather boxes for the top-200; zero the padded sup array
    for (int k = tid; k < (TOPK + 1) * KW8 / 4; k += NTHR)
        ((uint4*)sup)[k] = make_uint4(0u, 0u, 0u, 0u);
    for (int k = tid; k < n_top; k += NTHR) {
        unsigned long long key = keys[k];
        int idx = (int)(~(unsigned int)(key & 0xffffffffull));
        float4 bb = ((const float4*)boxes)[(size_t)b * ROWS + idx];
        s_box4[k] = bb;
        s_area[k] = (bb.z - bb.x) * (bb.w - bb.y);
        s_sc[k]   = __uint_as_float((unsigned int)(key >> 32));
    }
    __syncthreads();

    // ---- Suppression bitmask: one warp per row, ballot per 32-bit word.
    if (n_top > 0) {
        const int wlast = (n_top - 1) >> 5;
        for (int r = wid; r < n_top; r += (NTHR / 32)) {
            const float4 bi = s_box4[r];
            const float  ai = s_area[r];
            const int    w0 = r >> 5;
            {   // diagonal word
                int j = (w0 << 5) + lane;
                bool hit = false;
                if (j > r && j < n_top) {
                    float4 bj = s_box4[j];
                    float xx1 = fmaxf(bi.x, bj.x), yy1 = fmaxf(bi.y, bj.y);
                    float xx2 = fminf(bi.z, bj.z), yy2 = fminf(bi.w, bj.w);
                    float inter = fmaxf(0.f, xx2 - xx1) * fmaxf(0.f, yy2 - yy1);
                    if (inter > 0.f) {
                        float un = (ai + s_area[j]) - inter;
                        hit = (inter / un) > 0.5f;
                    }
                }
                unsigned int m = __ballot_sync(0xffffffffu, hit);
                if (lane == 0) sup[r * KW8 + w0] = m;
            }
            for (int w = w0 + 1; w < wlast; w++) {   // full middle words
                int j = (w << 5) + lane;
                float4 bj = s_box4[j];
                float xx1 = fmaxf(bi.x, bj.x), yy1 = fmaxf(bi.y, bj.y);
                float xx2 = fminf(bi.z, bj.z), yy2 = fminf(bi.w, bj.w);
                float inter = fmaxf(0.f, xx2 - xx1) * fmaxf(0.f, yy2 - yy1);
                bool hit = false;
                if (inter > 0.f) {
                    float un = (ai + s_area[j]) - inter;
                    hit = (inter / un) > 0.5f;
                }
                unsigned int m = __ballot_sync(0xffffffffu, hit);
                if (lane == 0) sup[r * KW8 + w] = m;
            }
            if (wlast > w0) {   // last (possibly partial) word
                int j = (wlast << 5) + lane;
                bool hit = false;
                if (j < n_top) {
                    float4 bj = s_box4[j];
                    float xx1 = fmaxf(bi.x, bj.x), yy1 = fmaxf(bi.y, bj.y);
                    float xx2 = fminf(bi.z, bj.z), yy2 = fminf(bi.w, bj.w);
                    float inter = fmaxf(0.f, xx2 - xx1) * fmaxf(0.f, yy2 - yy1);
                    if (inter > 0.f) {
                        float un = (ai + s_area[j]) - inter;
                        hit = (inter / un) > 0.5f;
                    }
                }
                unsigned int m = __ballot_sync(0xffffffffu, hit);
                if (lane == 0) sup[r * KW8 + wlast] = m;
            }
        }
    }
    __syncthreads();

    // ---- Serial greedy on thread 0: rows as 2x uint4, prefetch row i+1.
    if (tid == 0) {
        const uint4* sv = (const uint4*)sup;
        unsigned int rem[KW8];
        #pragma unroll
        for (int w = 0; w < KW8; w++) rem[w] = 0u;
        uint4 n0 = sv[0], n1 = sv[1];
        #pragma unroll
        for (int w0 = 0; w0 < KW; w0++) {
            for (int ii = 0; ii < 32; ii++) {
                int idx = w0 * 32 + ii;
                if (idx >= n_top) break;
                uint4 c0 = n0, c1 = n1;
                n0 = sv[(idx + 1) * 2];
                n1 = sv[(idx + 1) * 2 + 1];
                if (((rem[w0] >> ii) & 1u) == 0u) {
                    rem[0] |= c0.x; rem[1] |= c0.y; rem[2] |= c0.z; rem[3] |= c0.w;
                    rem[4] |= c1.x; rem[5] |= c1.y; rem[6] |= c1.z;
                }
            }
        }
        #pragma unroll
        for (int w = 0; w < KW; w++) s_keepw[w] = ~rem[w];
        g_ccnt[bc] = 0;   // self-clean for next replay
    }
    __syncthreads();

    // ---- Stage output rows in smem (reusing keys as scratch), then
    //      coalesced float4 copy to global.
    float* s_out = (float*)keys;   // 4800 B needed, 8192 B available
    if (tid < TOPK) {
        int k = tid;
        bool kp = (k < n_top) && (((s_keepw[k >> 5] >> (k & 31)) & 1u) != 0u);
        float4 bb = s_box4[k];
        float sc = s_sc[k], cl = (float)c;
        if (!kp) { bb = make_float4(0.f, 0.f, 0.f, 0.f); sc = 0.f; cl = 0.f; }
        s_out[k * 6 + 0] = bb.x; s_out[k * 6 + 1] = bb.y;
        s_out[k * 6 + 2] = bb.z; s_out[k * 6 + 3] = bb.w;
        s_out[k * 6 + 4] = sc;   s_out[k * 6 + 5] = cl;
    }
    __syncthreads();
    float4* o4 = (float4*)(out + (size_t)bc * (TOPK * 6));
    const float4* si4 = (const float4*)s_out;
    for (int t = tid; t < TOPK * 6 / 4; t += NTHR) o4[t] = si4[t];
}

// ---------------------------------------------------------------------------
extern "C" void kernel_launch(void* const* d_in, const int* in_sizes, int n_in,
                              void* d_out, int out_size) {
    const float* boxes  = (const float*)d_in[0];
    const float* scores = (const float*)d_in[1];
    if (n_in >= 2 && in_sizes[0] > in_sizes[1]) {  // scores is the bigger tensor
        boxes  = (const float*)d_in[1];
        scores = (const float*)d_in[0];
    }
    float* out = (float*)d_out;

    fused_kernel<<<NBC, NTHR>>>((const float4*)scores, boxes, scores, out);
}

// round 13
// speedup vs baseline: 1.0156x; 1.0156x over previous
#include <cuda_runtime.h>
#include <stdint.h>

#define NBATCH 8
#define NCLS   80
#define ROWS   17328                  // A*HW = 3*5776
#define PERB   (ROWS * NCLS)          // 1386240 elements per batch
#define PERB4  (PERB / 4)             // 346560 float4 per batch
#define SLICE4 (PERB4 / NCLS)         // 4332 float4 per CTA scatter slice
#define NTHR   320
#define TOPK   200
#define CAP    1024                   // staging / sort buffer capacity
#define CAP_G  768                    // global per-(b,c) candidate list capacity
#define KW     7                      // words actually used for bitmasks
#define KW8    8                      // padded stride (uint4 x2 per row)
#define NBC    (NBATCH * NCLS)
#define NFINE  9
#define NLAD   11
#define TH     0.98f

// Global scratch (static, zero-initialized at module load)
__device__ unsigned long long g_cand[NBC * CAP_G];   // ~3.9 MB
__device__ int g_ccnt[NBC];                          // reset by each CTA at end
__device__ int g_done[NBATCH];                       // monotonic barrier counters

__device__ __forceinline__ unsigned long long make_key(unsigned int scbits, int row) {
    return ((unsigned long long)scbits << 32) | (unsigned int)(~row);
}

// Cold path: staging overflow -> push straight to the per-(b,c) global list.
__device__ __noinline__ void direct_push(unsigned long long pk, int b) {
    unsigned int rem = (unsigned int)pk;
    int row = rem / NCLS;
    int cls = rem - row * NCLS;
    int dbc = b * NCLS + cls;
    int pos = atomicAdd(&g_ccnt[dbc], 1);
    if (pos < CAP_G)
        g_cand[dbc * CAP_G + pos] = make_key((unsigned int)(pk >> 32), row);
}

// Hot path: 4-bit hitmask + warp-uniform vote loop; one divergent block/round.
__device__ __forceinline__ void scan4(float4 v, int e0,
                                      unsigned long long* stage, int* scnt, int b) {
    unsigned int h = (v.x > TH ? 1u : 0u) | (v.y > TH ? 2u : 0u)
                   | (v.z > TH ? 4u : 0u) | (v.w > TH ? 8u : 0u);
    while (__any_sync(0xffffffffu, h)) {
        bool act = (h != 0u);
        int u = __ffs(h) - 1;
        h &= h - 1;
        if (act) {
            float val = (u == 0) ? v.x : (u == 1) ? v.y : (u == 2) ? v.z : v.w;
            unsigned long long pk =
                ((unsigned long long)__float_as_uint(val) << 32) | (unsigned int)(e0 + u);
            int pos = atomicAdd(scnt, 1);
            if (pos < CAP) stage[pos] = pk;
            else direct_push(pk, b);
        }
    }
}

// ---------------------------------------------------------------------------
// Fused kernel: one CTA per (batch, class).
// Phase 1: scan 1/80 of this batch's scores into SMEM staging, then distribute
//          staged candidates to per-(b,c) global lists.
// Phase 2: per-batch barrier, then pivot-refine + sort + greedy NMS.
// ---------------------------------------------------------------------------
__global__ void __launch_bounds__(NTHR, 5)
fused_kernel(const float4* __restrict__ s4,
             const float*  __restrict__ boxes,
             const float*  __restrict__ scores,
             float*        __restrict__ out) {
    const int tid  = threadIdx.x;
    const int lane = tid & 31;
    const int wid  = tid >> 5;
    const int bc   = blockIdx.x;
    const int b    = bc / NCLS;
    const int c    = bc % NCLS;

    __shared__ unsigned long long keys[CAP];         // staging, then sort buffer
    __shared__ float4 s_box4[TOPK];
    __shared__ float s_area[TOPK], s_sc[TOPK];
    __shared__ unsigned int sup[(TOPK + 1) * KW8];
    __shared__ unsigned int s_keepw[KW];
    __shared__ int s_num, s_fcnt[NFINE], s_pcnt[NLAD];

    // ================= Phase 1: scan slice into SMEM staging =================
    if (tid == 0) s_num = 0;
    __syncthreads();
    {
        const float4* p = s4 + (size_t)bc * SLICE4;  // b*PERB4 + c*SLICE4
        const int rbase = c * (SLICE4 * 4);          // batch-relative element base
        #pragma unroll
        for (int g = 0; g < 3; g++) {
            int i0 = tid + g * (4 * NTHR);
            float4 v0 = __ldcs(&p[i0]);
            float4 v1 = __ldcs(&p[i0 + NTHR]);
            float4 v2 = __ldcs(&p[i0 + 2 * NTHR]);
            float4 v3 = __ldcs(&p[i0 + 3 * NTHR]);
            scan4(v0, rbase + i0 * 4,              keys, &s_num, b);
            scan4(v1, rbase + (i0 + NTHR) * 4,     keys, &s_num, b);
            scan4(v2, rbase + (i0 + 2 * NTHR) * 4, keys, &s_num, b);
            scan4(v3, rbase + (i0 + 3 * NTHR) * 4, keys, &s_num, b);
        }
        {   // iterations 12 (full) and 13 (guarded): 14*320 = 4480 >= 4332
            int i0 = tid + 12 * NTHR;
            int i1 = tid + 13 * NTHR;
            float4 v0 = __ldcs(&p[i0]);
            float4 v1 = (i1 < SLICE4) ? __ldcs(&p[i1])
                                      : make_float4(0.f, 0.f, 0.f, 0.f);
            scan4(v0, rbase + i0 * 4, keys, &s_num, b);
            scan4(v1, rbase + i1 * 4, keys, &s_num, b);
        }
    }
    __syncthreads();
    // ---- Distribute staged candidates to per-(b,c) global lists.
    {
        int nstage = s_num; if (nstage > CAP) nstage = CAP;
        for (int k = tid; k < nstage; k += NTHR) {
            unsigned long long pk = keys[k];
            unsigned int rem = (unsigned int)pk;
            int row = rem / NCLS;
            int cls = rem - row * NCLS;
            int dbc = b * NCLS + cls;
            int pos = atomicAdd(&g_ccnt[dbc], 1);
            if (pos < CAP_G)
                g_cand[dbc * CAP_G + pos] = make_key((unsigned int)(pk >> 32), row);
        }
    }
    // ---- Per-batch barrier: 80 arrivals on a monotonic counter.
    __syncthreads();
    if (tid == 0) {
        __threadfence();
        int old = atomicAdd(&g_done[b], 1);
        int target = old - (old % NCLS) + NCLS;
        const volatile int* dp = (const volatile int*)&g_done[b];
        while (*dp < target) __nanosleep(64);
        __threadfence();
    }
    __syncthreads();

    // ================= Phase 2: NMS for (b, c) =================
    const int cnt098 = g_ccnt[bc];

    if (tid < NFINE) s_fcnt[tid] = 0;
    if (tid == 0) s_num = 0;
    __syncthreads();

    int cnt;
    if (cnt098 >= TOPK && cnt098 <= CAP_G) {
        // ---- Fast path: list is complete and holds >= 200 candidates.
        unsigned long long kreg[3];
        const unsigned long long* src = g_cand + (size_t)bc * CAP_G;
        #pragma unroll
        for (int r = 0; r < 3; r++) {
            int k = tid + r * NTHR;
            kreg[r] = (k < cnt098) ? src[k] : 0ull;
        }
        const float FL[NFINE] = {0.99500f, 0.99375f, 0.99250f, 0.99125f, 0.99000f,
                                 0.98875f, 0.98750f, 0.98625f, 0.98500f};
        int lc[NFINE];
        #pragma unroll
        for (int f = 0; f < NFINE; f++) lc[f] = 0;
        #pragma unroll
        for (int r = 0; r < 3; r++) {
            float sc = __uint_as_float((unsigned int)(kreg[r] >> 32));
            #pragma unroll
            for (int f = 0; f < NFINE; f++) lc[f] += (sc > FL[f]);
        }
        #pragma unroll
        for (int f = 0; f < NFINE; f++) {
            int ws = __reduce_add_sync(0xffffffffu, lc[f]);
            if (lane == 0 && ws) atomicAdd(&s_fcnt[f], ws);
        }
        __syncthreads();
        float pivot = TH;
        #pragma unroll
        for (int f = NFINE - 1; f >= 0; f--)
            if (s_fcnt[f] >= TOPK) pivot = FL[f];
        #pragma unroll
        for (int r = 0; r < 3; r++) {
            float sc = __uint_as_float((unsigned int)(kreg[r] >> 32));
            if (sc > pivot) {
                int pos = atomicAdd(&s_num, 1);
                keys[pos] = kreg[r];
            }
        }
        __syncthreads();
        cnt = s_num;
    } else {
        // ---- Fallback (statistically never): full strided rescan with ladder.
        if (tid < NLAD) s_pcnt[tid] = 0;
        __syncthreads();
        const float PL[NLAD] = {0.9950f, 0.9925f, 0.9900f, 0.9875f, 0.9850f,
                                0.98f, 0.96f, 0.92f, 0.84f, 0.68f, 0.50f};
        const float* col = scores + (size_t)b * PERB + c;
        int lc[NLAD];
        #pragma unroll
        for (int l = 0; l < NLAD; l++) lc[l] = 0;
        for (int i = tid; i < ROWS; i += NTHR) {
            float v = col[(size_t)i * NCLS];
            #pragma unroll
            for (int l = 0; l < NLAD; l++) lc[l] += (v > PL[l]);
        }
        #pragma unroll
        for (int l = 0; l < NLAD; l++) {
            int ws = __reduce_add_sync(0xffffffffu, lc[l]);
            if (lane == 0 && ws) atomicAdd(&s_pcnt[l], ws);
        }
        __syncthreads();
        const int n05 = s_pcnt[NLAD - 1];
        const int target = (n05 < TOPK) ? n05 : TOPK;
        float pivot = 0.50f;
        #pragma unroll
        for (int l = NLAD - 1; l >= 0; l--)
            if (s_pcnt[l] >= target) pivot = PL[l];
        for (int i = tid; i < ROWS; i += NTHR) {
            float v = col[(size_t)i * NCLS];
            if (v > pivot) {
                int pos = atomicAdd(&s_num, 1);
                if (pos < CAP) keys[pos] = make_key(__float_as_uint(v), i);
            }
        }
        __syncthreads();
        cnt = s_num; if (cnt > CAP) cnt = CAP;
    }

    // ---- Sort descending. Register/shuffle bitonic on threads 0..255.
    if (cnt <= 256) {
        for (int i = cnt + tid; i < 256; i += NTHR) keys[i] = 0ull;
        __syncthreads();
        unsigned long long key = (tid < 256) ? keys[tid] : 0ull;
        #pragma unroll
        for (int k = 2; k <= 256; k <<= 1) {
            #pragma unroll
            for (int j = k >> 1; j > 0; j >>= 1) {
                unsigned long long other;
                if (j >= 32) {
                    if (tid < 256) keys[tid] = key;
                    __syncthreads();
                    other = (tid < 256) ? keys[tid ^ j] : 0ull;
                    __syncthreads();
                } else {
                    other = __shfl_xor_sync(0xffffffffu, key, j);
                }
                bool keep_max = ((tid & k) == 0) == ((tid & j) == 0);
                key = ((key > other) == keep_max) ? key : other;
            }
        }
        if (tid < 256) keys[tid] = key;
        __syncthreads();
    } else {
        int P = 512; while (P < cnt) P <<= 1;
        for (int i = cnt + tid; i < P; i += NTHR) keys[i] = 0ull;
        __syncthreads();
        for (int k = 2; k <= P; k <<= 1) {
            for (int j = k >> 1; j > 0; j >>= 1) {
                for (int i = tid; i < P; i += NTHR) {
                    int l = i ^ j;
                    if (l > i) {
                        unsigned long long a = keys[i], d = keys[l];
                        bool sw = ((i & k) == 0) ? (a < d) : (a > d);
                        if (sw) { keys[i] = d; keys[l] = a; }
                    }
                }
                __syncthreads();
            }
        }
    }

    const int n_top = (cnt < TOPK) ? cnt : TOPK;

    // ---- Gather boxes for the top-200; zero the padded sup array
    for (int k = tid; k < (TOPK + 1) * KW8 / 4; k += NTHR)
        ((uint4*)sup)[k] = make_uint4(0u, 0u, 0u, 0u);
    for (int k = tid; k < n_top; k += NTHR) {
        unsigned long long key = keys[k];
        int idx = (int)(~(unsigned int)(key & 0xffffffffull));
        float4 bb = ((const float4*)boxes)[(size_t)b * ROWS + idx];
        s_box4[k] = bb;
        s_area[k] = (bb.z - bb.x) * (bb.w - bb.y);
        s_sc[k]   = __uint_as_float((unsigned int)(key >> 32));
    }
    __syncthreads();

    // ---- Suppression bitmask: one warp per row, ballot per 32-bit word.
    if (n_top > 0) {
        const int wlast = (n_top - 1) >> 5;
        for (int r = wid; r < n_top; r += (NTHR / 32)) {
            const float4 bi = s_box4[r];
            const float  ai = s_area[r];
            const int    w0 = r >> 5;
            {   // diagonal word
                int j = (w0 << 5) + lane;
                bool hit = false;
                if (j > r && j < n_top) {
                    float4 bj = s_box4[j];
                    float xx1 = fmaxf(bi.x, bj.x), yy1 = fmaxf(bi.y, bj.y);
                    float xx2 = fminf(bi.z, bj.z), yy2 = fminf(bi.w, bj.w);
                    float inter = fmaxf(0.f, xx2 - xx1) * fmaxf(0.f, yy2 - yy1);
                    if (inter > 0.f) {
                        float un = (ai + s_area[j]) - inter;
                        hit = (inter / un) > 0.5f;
                    }
                }
                unsigned int m = __ballot_sync(0xffffffffu, hit);
                if (lane == 0) sup[r * KW8 + w0] = m;
            }
            for (int w = w0 + 1; w < wlast; w++) {   // full middle words
                int j = (w << 5) + lane;
                float4 bj = s_box4[j];
                float xx1 = fmaxf(bi.x, bj.x), yy1 = fmaxf(bi.y, bj.y);
                float xx2 = fminf(bi.z, bj.z), yy2 = fminf(bi.w, bj.w);
                float inter = fmaxf(0.f, xx2 - xx1) * fmaxf(0.f, yy2 - yy1);
                bool hit = false;
                if (inter > 0.f) {
                    float un = (ai + s_area[j]) - inter;
                    hit = (inter / un) > 0.5f;
                }
                unsigned int m = __ballot_sync(0xffffffffu, hit);
                if (lane == 0) sup[r * KW8 + w] = m;
            }
            if (wlast > w0) {   // last (possibly partial) word
                int j = (wlast << 5) + lane;
                bool hit = false;
                if (j < n_top) {
                    float4 bj = s_box4[j];
                    float xx1 = fmaxf(bi.x, bj.x), yy1 = fmaxf(bi.y, bj.y);
                    float xx2 = fminf(bi.z, bj.z), yy2 = fminf(bi.w, bj.w);
                    float inter = fmaxf(0.f, xx2 - xx1) * fmaxf(0.f, yy2 - yy1);
                    if (inter > 0.f) {
                        float un = (ai + s_area[j]) - inter;
                        hit = (inter / un) > 0.5f;
                    }
                }
                unsigned int m = __ballot_sync(0xffffffffu, hit);
                if (lane == 0) sup[r * KW8 + wlast] = m;
            }
        }
    }
    __syncthreads();

    // ---- Serial greedy on thread 0: rows as 2x uint4, prefetch row i+1.
    if (tid == 0) {
        const uint4* sv = (const uint4*)sup;
        unsigned int rem[KW8];
        #pragma unroll
        for (int w = 0; w < KW8; w++) rem[w] = 0u;
        uint4 n0 = sv[0], n1 = sv[1];
        #pragma unroll
        for (int w0 = 0; w0 < KW; w0++) {
            for (int ii = 0; ii < 32; ii++) {
                int idx = w0 * 32 + ii;
                if (idx >= n_top) break;
                uint4 c0 = n0, c1 = n1;
                n0 = sv[(idx + 1) * 2];
                n1 = sv[(idx + 1) * 2 + 1];
                if (((rem[w0] >> ii) & 1u) == 0u) {
                    rem[0] |= c0.x; rem[1] |= c0.y; rem[2] |= c0.z; rem[3] |= c0.w;
                    rem[4] |= c1.x; rem[5] |= c1.y; rem[6] |= c1.z;
                }
            }
        }
        #pragma unroll
        for (int w = 0; w < KW; w++) s_keepw[w] = ~rem[w];
        g_ccnt[bc] = 0;   // self-clean for next replay
    }
    __syncthreads();

    // ---- Stage output rows in smem (reusing keys as scratch), then
    //      coalesced float4 copy to global.
    float* s_out = (float*)keys;   // 4800 B needed, 8192 B available
    if (tid < TOPK) {
        int k = tid;
        bool kp = (k < n_top) && (((s_keepw[k >> 5] >> (k & 31)) & 1u) != 0u);
        float4 bb = s_box4[k];
        float sc = s_sc[k], cl = (float)c;
        if (!kp) { bb = make_float4(0.f, 0.f, 0.f, 0.f); sc = 0.f; cl = 0.f; }
        s_out[k * 6 + 0] = bb.x; s_out[k * 6 + 1] = bb.y;
        s_out[k * 6 + 2] = bb.z; s_out[k * 6 + 3] = bb.w;
        s_out[k * 6 + 4] = sc;   s_out[k * 6 + 5] = cl;
    }
    __syncthreads();
    float4* o4 = (float4*)(out + (size_t)bc * (TOPK * 6));
    const float4* si4 = (const float4*)s_out;
    for (int t = tid; t < TOPK * 6 / 4; t += NTHR) o4[t] = si4[t];
}

// ---------------------------------------------------------------------------
extern "C" void kernel_launch(void* const* d_in, const int* in_sizes, int n_in,
                              void* d_out, int out_size) {
    const float* boxes  = (const float*)d_in[0];
    const float* scores = (const float*)d_in[1];
    if (n_in >= 2 && in_sizes[0] > in_sizes[1]) {  // scores is the bigger tensor
        boxes  = (const float*)d_in[1];
        scores = (const float*)d_in[0];
    }
    float* out = (float*)d_out;

    fused_kernel<<<NBC, NTHR>>>((const float4*)scores, boxes, scores, out);
}